// round 1
// baseline (speedup 1.0000x reference)
#include <cuda_runtime.h>
#include <cstdint>

// Problem constants
#define T_TOK   4096          // B*S tokens
#define D_MODEL 1024
#define DFF     2048
#define NROUTED 7             // E-1 routed experts
#define BM      128
#define NTILES_M 104
#define R_MAX   (NTILES_M * BM)   // 13312 padded rows (T + 2T routed + per-expert pad)

// ---------------- scratch (static device globals; no allocations) -------------
__device__ float d_H[(size_t)R_MAX * DFF];   // SwiGLU hidden, ~109 MB
__device__ int   d_tok[R_MAX];               // row -> token (-1 = padding)
__device__ float d_wrow[R_MAX];              // row -> combine weight
__device__ int   d_off[8];                   // region starts; d_off[7] = end
__device__ int   d_cnt[NROUTED];
__device__ int   d_cnt2[NROUTED];
__device__ int   d_topi[T_TOK * 2];
__device__ float d_topw[T_TOK * 2];

// ---------------- helpers ----------------------------------------------------
__device__ __forceinline__ uint32_t f2tf(float f) {
    uint32_t r;
    asm("cvt.rna.tf32.f32 %0, %1;" : "=r"(r) : "f"(f));
    return r;
}

__device__ __forceinline__ void mma8(float c[4], const uint32_t a[4], const uint32_t b[2]) {
    asm volatile(
        "mma.sync.aligned.m16n8k8.row.col.f32.tf32.tf32.f32 "
        "{%0,%1,%2,%3}, {%4,%5,%6,%7}, {%8,%9}, {%0,%1,%2,%3};\n"
        : "+f"(c[0]), "+f"(c[1]), "+f"(c[2]), "+f"(c[3])
        : "r"(a[0]), "r"(a[1]), "r"(a[2]), "r"(a[3]), "r"(b[0]), "r"(b[1]));
}

// ---------------- kernel 1: init ---------------------------------------------
__global__ void init_kernel(float* __restrict__ out) {
    int stride = gridDim.x * blockDim.x;
    int i = blockIdx.x * blockDim.x + threadIdx.x;
    for (int j = i; j < T_TOK * D_MODEL; j += stride) out[j] = 0.f;
    for (int j = i; j < R_MAX; j += stride) {
        if (j < T_TOK) { d_tok[j] = j;  d_wrow[j] = 1.f; }
        else           { d_tok[j] = -1; d_wrow[j] = 0.f; }
    }
    if (i < NROUTED) { d_cnt[i] = 0; d_cnt2[i] = 0; }
}

// ---------------- kernel 2: router (1 warp per token) -------------------------
__global__ void router_kernel(const float* __restrict__ x,
                              const float* __restrict__ rw,
                              const float* __restrict__ rb) {
    int gw = (blockIdx.x * blockDim.x + threadIdx.x) >> 5;
    int lane = threadIdx.x & 31;
    if (gw >= T_TOK) return;
    const float* xr = x + (size_t)gw * D_MODEL;
    float acc[NROUTED];
#pragma unroll
    for (int j = 0; j < NROUTED; j++) acc[j] = 0.f;
    for (int k = lane; k < D_MODEL; k += 32) {
        float xv = xr[k];
        const float* w = rw + k * NROUTED;
#pragma unroll
        for (int j = 0; j < NROUTED; j++) acc[j] += xv * w[j];
    }
#pragma unroll
    for (int j = 0; j < NROUTED; j++) {
#pragma unroll
        for (int o = 16; o > 0; o >>= 1)
            acc[j] += __shfl_xor_sync(0xffffffffu, acc[j], o);
    }
    if (lane == 0) {
        float lg[NROUTED];
#pragma unroll
        for (int j = 0; j < NROUTED; j++) lg[j] = acc[j] + rb[j];
        int i1 = 0;
#pragma unroll
        for (int j = 1; j < NROUTED; j++) if (lg[j] > lg[i1]) i1 = j;
        int i2 = (i1 == 0) ? 1 : 0;
#pragma unroll
        for (int j = 0; j < NROUTED; j++)
            if (j != i1 && lg[j] > lg[i2]) i2 = j;
        // softmax-over-top2 == renormalized top-2 of full softmax
        float m  = fmaxf(lg[i1], lg[i2]);
        float e1 = expf(lg[i1] - m), e2 = expf(lg[i2] - m);
        float s  = e1 + e2;
        d_topi[gw * 2]     = i1;  d_topi[gw * 2 + 1] = i2;
        d_topw[gw * 2]     = e1 / s;
        d_topw[gw * 2 + 1] = e2 / s;
        atomicAdd(&d_cnt[i1], 1);
        atomicAdd(&d_cnt[i2], 1);
    }
}

// ---------------- kernel 3: offsets (tiny, 1 thread) --------------------------
__global__ void offsets_kernel() {
    if (threadIdx.x == 0 && blockIdx.x == 0) {
        int base = T_TOK;
        for (int j = 0; j < NROUTED; j++) {
            d_off[j] = base;
            base += ((d_cnt[j] + BM - 1) / BM) * BM;
        }
        d_off[7] = base;
    }
}

// ---------------- kernel 4: fill gathered row tables --------------------------
__global__ void fill_kernel() {
    int i = blockIdx.x * blockDim.x + threadIdx.x;
    if (i >= T_TOK * 2) return;
    int t = i >> 1;
    int e = d_topi[i];
    float w = d_topw[i];
    int p = atomicAdd(&d_cnt2[e], 1);
    int r = d_off[e] + p;
    d_tok[r]  = t;
    d_wrow[r] = w;
}

// ---------------- region lookup ----------------------------------------------
__device__ __forceinline__ int tile_expert(int row0) {
    if (row0 < T_TOK) return 0;
    int e = 0;
#pragma unroll
    for (int j = 0; j < NROUTED; j++)
        if (row0 >= d_off[j] && row0 < d_off[j + 1]) e = j + 1;
    return e;
}

// ---------------- kernel 5: fused gate+up GEMM + SiLU*u -> H -------------------
// C-tile: BM=128 rows x BN=64 ff-cols, for BOTH wg and wu. 8 warps (4m x 2n),
// warp tile 32x32 per accumulator set. TF32 mma m16n8k8, BK=32.
__global__ __launch_bounds__(256, 2) void gemm1_kernel(
    const float* __restrict__ x,
    const float* __restrict__ wg,
    const float* __restrict__ wu) {
    int row0 = blockIdx.x * BM;
    if (row0 >= d_off[7]) return;
    int e = tile_expert(row0);
    const float* bg = wg + (size_t)e * D_MODEL * DFF;
    const float* bu = wu + (size_t)e * D_MODEL * DFF;
    int n0 = blockIdx.y * 64;

    __shared__ uint32_t sA[128][36];
    __shared__ uint32_t sBg[32][68];
    __shared__ uint32_t sBu[32][68];
    __shared__ int stok[128];

    int tid = threadIdx.x;
    if (tid < 128) stok[tid] = d_tok[row0 + tid];
    __syncthreads();

    int warp = tid >> 5, lane = tid & 31;
    int wm = (warp >> 1) * 32, wn = (warp & 1) * 32;

    float accG[2][4][4], accU[2][4][4];
#pragma unroll
    for (int mi = 0; mi < 2; mi++)
#pragma unroll
        for (int ni = 0; ni < 4; ni++)
#pragma unroll
            for (int r = 0; r < 4; r++) { accG[mi][ni][r] = 0.f; accU[mi][ni][r] = 0.f; }

    for (int k0 = 0; k0 < D_MODEL; k0 += 32) {
        // A tile: 128x32 gathered token rows (tf32-rounded)
#pragma unroll
        for (int i = 0; i < 4; i++) {
            int f = tid + i * 256;
            int r = f >> 3, c = (f & 7) << 2;
            int tok = stok[r];
            float4 v = make_float4(0.f, 0.f, 0.f, 0.f);
            if (tok >= 0) v = *(const float4*)(x + (size_t)tok * D_MODEL + k0 + c);
            sA[r][c] = f2tf(v.x); sA[r][c + 1] = f2tf(v.y);
            sA[r][c + 2] = f2tf(v.z); sA[r][c + 3] = f2tf(v.w);
        }
        // B tiles: 32x64 each from wg and wu
#pragma unroll
        for (int i = 0; i < 2; i++) {
            int f = tid + i * 256;
            int r = f >> 4, c = (f & 15) << 2;
            float4 g = *(const float4*)(bg + (size_t)(k0 + r) * DFF + n0 + c);
            float4 u = *(const float4*)(bu + (size_t)(k0 + r) * DFF + n0 + c);
            sBg[r][c] = f2tf(g.x); sBg[r][c + 1] = f2tf(g.y);
            sBg[r][c + 2] = f2tf(g.z); sBg[r][c + 3] = f2tf(g.w);
            sBu[r][c] = f2tf(u.x); sBu[r][c + 1] = f2tf(u.y);
            sBu[r][c + 2] = f2tf(u.z); sBu[r][c + 3] = f2tf(u.w);
        }
        __syncthreads();
#pragma unroll
        for (int kk = 0; kk < 32; kk += 8) {
            uint32_t a[2][4];
#pragma unroll
            for (int mi = 0; mi < 2; mi++) {
                int rb = wm + mi * 16 + (lane >> 2);
                int cb = kk + (lane & 3);
                a[mi][0] = sA[rb][cb];     a[mi][1] = sA[rb + 8][cb];
                a[mi][2] = sA[rb][cb + 4]; a[mi][3] = sA[rb + 8][cb + 4];
            }
#pragma unroll
            for (int ni = 0; ni < 4; ni++) {
                int nb = wn + ni * 8 + (lane >> 2);
                int kb = kk + (lane & 3);
                uint32_t bgf[2] = { sBg[kb][nb], sBg[kb + 4][nb] };
                uint32_t buf[2] = { sBu[kb][nb], sBu[kb + 4][nb] };
#pragma unroll
                for (int mi = 0; mi < 2; mi++) {
                    mma8(accG[mi][ni], a[mi], bgf);
                    mma8(accU[mi][ni], a[mi], buf);
                }
            }
        }
        __syncthreads();
    }
    // epilogue: H = silu(g) * u
#pragma unroll
    for (int mi = 0; mi < 2; mi++)
#pragma unroll
        for (int ni = 0; ni < 4; ni++)
#pragma unroll
            for (int rr = 0; rr < 4; rr++) {
                int rl = wm + mi * 16 + (lane >> 2) + ((rr >= 2) ? 8 : 0);
                if (stok[rl] < 0) continue;
                int col = n0 + wn + ni * 8 + 2 * (lane & 3) + (rr & 1);
                float g = accG[mi][ni][rr], u = accU[mi][ni][rr];
                float h = (g / (1.f + __expf(-g))) * u;
                d_H[(size_t)(row0 + rl) * DFF + col] = h;
            }
}

// ---------------- kernel 6: down GEMM + weighted scatter-add -------------------
__global__ __launch_bounds__(256, 2) void gemm2_kernel(
    const float* __restrict__ wd, float* __restrict__ out) {
    int row0 = blockIdx.x * BM;
    if (row0 >= d_off[7]) return;
    int e = tile_expert(row0);
    const float* bw = wd + (size_t)e * DFF * D_MODEL;
    int n0 = blockIdx.y * 64;

    __shared__ uint32_t sA[128][36];
    __shared__ uint32_t sB[32][68];
    __shared__ int stok[128];
    __shared__ float swt[128];

    int tid = threadIdx.x;
    if (tid < 128) { stok[tid] = d_tok[row0 + tid]; swt[tid] = d_wrow[row0 + tid]; }
    __syncthreads();

    int warp = tid >> 5, lane = tid & 31;
    int wm = (warp >> 1) * 32, wn = (warp & 1) * 32;

    float acc[2][4][4];
#pragma unroll
    for (int mi = 0; mi < 2; mi++)
#pragma unroll
        for (int ni = 0; ni < 4; ni++)
#pragma unroll
            for (int r = 0; r < 4; r++) acc[mi][ni][r] = 0.f;

    for (int k0 = 0; k0 < DFF; k0 += 32) {
#pragma unroll
        for (int i = 0; i < 4; i++) {
            int f = tid + i * 256;
            int r = f >> 3, c = (f & 7) << 2;
            float4 v = make_float4(0.f, 0.f, 0.f, 0.f);
            if (stok[r] >= 0) v = *(const float4*)(d_H + (size_t)(row0 + r) * DFF + k0 + c);
            sA[r][c] = f2tf(v.x); sA[r][c + 1] = f2tf(v.y);
            sA[r][c + 2] = f2tf(v.z); sA[r][c + 3] = f2tf(v.w);
        }
#pragma unroll
        for (int i = 0; i < 2; i++) {
            int f = tid + i * 256;
            int r = f >> 4, c = (f & 15) << 2;
            float4 b = *(const float4*)(bw + (size_t)(k0 + r) * D_MODEL + n0 + c);
            sB[r][c] = f2tf(b.x); sB[r][c + 1] = f2tf(b.y);
            sB[r][c + 2] = f2tf(b.z); sB[r][c + 3] = f2tf(b.w);
        }
        __syncthreads();
#pragma unroll
        for (int kk = 0; kk < 32; kk += 8) {
            uint32_t a[2][4];
#pragma unroll
            for (int mi = 0; mi < 2; mi++) {
                int rb = wm + mi * 16 + (lane >> 2);
                int cb = kk + (lane & 3);
                a[mi][0] = sA[rb][cb];     a[mi][1] = sA[rb + 8][cb];
                a[mi][2] = sA[rb][cb + 4]; a[mi][3] = sA[rb + 8][cb + 4];
            }
#pragma unroll
            for (int ni = 0; ni < 4; ni++) {
                int nb = wn + ni * 8 + (lane >> 2);
                int kb = kk + (lane & 3);
                uint32_t bf[2] = { sB[kb][nb], sB[kb + 4][nb] };
#pragma unroll
                for (int mi = 0; mi < 2; mi++)
                    mma8(acc[mi][ni], a[mi], bf);
            }
        }
        __syncthreads();
    }
    // epilogue: out[token] += w_row * y  (RED.ADD, after zero-init)
#pragma unroll
    for (int mi = 0; mi < 2; mi++)
#pragma unroll
        for (int ni = 0; ni < 4; ni++)
#pragma unroll
            for (int rr = 0; rr < 4; rr++) {
                int rl = wm + mi * 16 + (lane >> 2) + ((rr >= 2) ? 8 : 0);
                int tok = stok[rl];
                if (tok < 0) continue;
                int col = n0 + wn + ni * 8 + 2 * (lane & 3) + (rr & 1);
                atomicAdd(out + (size_t)tok * D_MODEL + col, swt[rl] * acc[mi][ni][rr]);
            }
}

// ---------------- launch -------------------------------------------------------
extern "C" void kernel_launch(void* const* d_in, const int* in_sizes, int n_in,
                              void* d_out, int out_size) {
    const float* x  = (const float*)d_in[0];  // hidden_states [2,2048,1024]
    const float* rw = (const float*)d_in[1];  // router_w [1024,7]
    const float* rb = (const float*)d_in[2];  // router_b [7]
    const float* wg = (const float*)d_in[3];  // [8,1024,2048]
    const float* wu = (const float*)d_in[4];  // [8,1024,2048]
    const float* wd = (const float*)d_in[5];  // [8,2048,1024]
    float* out = (float*)d_out;               // [2,2048,1024] fp32
    (void)in_sizes; (void)n_in; (void)out_size; // top_k fixed = 2

    init_kernel<<<1024, 256>>>(out);
    router_kernel<<<512, 256>>>(x, rw, rb);
    offsets_kernel<<<1, 1>>>();
    fill_kernel<<<(T_TOK * 2 + 255) / 256, 256>>>();
    gemm1_kernel<<<dim3(NTILES_M, DFF / 64), 256>>>(x, wg, wu);
    gemm2_kernel<<<dim3(NTILES_M, D_MODEL / 64), 256>>>(wd, out);
}

// round 2
// speedup vs baseline: 1.6535x; 1.6535x over previous
#include <cuda_runtime.h>
#include <cstdint>

// Problem constants
#define T_TOK   4096          // B*S tokens
#define D_MODEL 1024
#define DFF     2048
#define NROUTED 7             // E-1 routed experts
#define BM      128
#define NTILES_M 104
#define R_MAX   (NTILES_M * BM)   // padded rows (T + 2T routed + per-expert pad)

// ---------------- scratch (static device globals; no allocations) -------------
__device__ float d_H[(size_t)R_MAX * DFF];   // SwiGLU hidden, ~109 MB
__device__ int   d_tok[R_MAX];               // row -> token (-1 = padding)
__device__ float d_wrow[R_MAX];              // row -> combine weight
__device__ int   d_off[8];                   // region starts; d_off[7] = end
__device__ int   d_cnt[NROUTED];
__device__ int   d_cnt2[NROUTED];
__device__ int   d_topi[T_TOK * 2];
__device__ float d_topw[T_TOK * 2];

// ---------------- helpers ----------------------------------------------------
__device__ __forceinline__ uint32_t f2tf(float f) {
    uint32_t r;
    asm("cvt.rna.tf32.f32 %0, %1;" : "=r"(r) : "f"(f));
    return r;
}

__device__ __forceinline__ void mma8(float c[4], const uint32_t a[4], const uint32_t b[2]) {
    asm volatile(
        "mma.sync.aligned.m16n8k8.row.col.f32.tf32.tf32.f32 "
        "{%0,%1,%2,%3}, {%4,%5,%6,%7}, {%8,%9}, {%0,%1,%2,%3};\n"
        : "+f"(c[0]), "+f"(c[1]), "+f"(c[2]), "+f"(c[3])
        : "r"(a[0]), "r"(a[1]), "r"(a[2]), "r"(a[3]), "r"(b[0]), "r"(b[1]));
}

// 16B cp.async with zero-fill when pred is false
__device__ __forceinline__ void cp16(float* dst, const float* src, bool pred) {
    uint32_t d = (uint32_t)__cvta_generic_to_shared(dst);
    int sz = pred ? 16 : 0;
    asm volatile("cp.async.cg.shared.global [%0], [%1], 16, %2;\n"
                 :: "r"(d), "l"(src), "r"(sz));
}
__device__ __forceinline__ void cp_commit() {
    asm volatile("cp.async.commit_group;\n");
}
__device__ __forceinline__ void cp_wait1() {
    asm volatile("cp.async.wait_group 1;\n");
}
__device__ __forceinline__ void cp_wait0() {
    asm volatile("cp.async.wait_group 0;\n");
}

// ---------------- kernel 1: init ---------------------------------------------
__global__ void init_kernel(float* __restrict__ out) {
    int stride = gridDim.x * blockDim.x;
    int i = blockIdx.x * blockDim.x + threadIdx.x;
    for (int j = i; j < T_TOK * D_MODEL; j += stride) out[j] = 0.f;
    for (int j = i; j < R_MAX; j += stride) {
        if (j < T_TOK) { d_tok[j] = j;  d_wrow[j] = 1.f; }
        else           { d_tok[j] = -1; d_wrow[j] = 0.f; }
    }
    if (i < NROUTED) { d_cnt[i] = 0; d_cnt2[i] = 0; }
}

// ---------------- kernel 2: router (1 warp per token) -------------------------
__global__ void router_kernel(const float* __restrict__ x,
                              const float* __restrict__ rw,
                              const float* __restrict__ rb) {
    int gw = (blockIdx.x * blockDim.x + threadIdx.x) >> 5;
    int lane = threadIdx.x & 31;
    if (gw >= T_TOK) return;
    const float* xr = x + (size_t)gw * D_MODEL;
    float acc[NROUTED];
#pragma unroll
    for (int j = 0; j < NROUTED; j++) acc[j] = 0.f;
    for (int k = lane; k < D_MODEL; k += 32) {
        float xv = xr[k];
        const float* w = rw + k * NROUTED;
#pragma unroll
        for (int j = 0; j < NROUTED; j++) acc[j] += xv * w[j];
    }
#pragma unroll
    for (int j = 0; j < NROUTED; j++) {
#pragma unroll
        for (int o = 16; o > 0; o >>= 1)
            acc[j] += __shfl_xor_sync(0xffffffffu, acc[j], o);
    }
    if (lane == 0) {
        float lg[NROUTED];
#pragma unroll
        for (int j = 0; j < NROUTED; j++) lg[j] = acc[j] + rb[j];
        int i1 = 0;
#pragma unroll
        for (int j = 1; j < NROUTED; j++) if (lg[j] > lg[i1]) i1 = j;
        int i2 = (i1 == 0) ? 1 : 0;
#pragma unroll
        for (int j = 0; j < NROUTED; j++)
            if (j != i1 && lg[j] > lg[i2]) i2 = j;
        float m  = fmaxf(lg[i1], lg[i2]);
        float e1 = expf(lg[i1] - m), e2 = expf(lg[i2] - m);
        float s  = e1 + e2;
        d_topi[gw * 2]     = i1;  d_topi[gw * 2 + 1] = i2;
        d_topw[gw * 2]     = e1 / s;
        d_topw[gw * 2 + 1] = e2 / s;
        atomicAdd(&d_cnt[i1], 1);
        atomicAdd(&d_cnt[i2], 1);
    }
}

// ---------------- kernel 3: offsets (tiny, 1 thread) --------------------------
__global__ void offsets_kernel() {
    if (threadIdx.x == 0 && blockIdx.x == 0) {
        int base = T_TOK;
        for (int j = 0; j < NROUTED; j++) {
            d_off[j] = base;
            base += ((d_cnt[j] + BM - 1) / BM) * BM;
        }
        d_off[7] = base;
    }
}

// ---------------- kernel 4: fill gathered row tables --------------------------
__global__ void fill_kernel() {
    int i = blockIdx.x * blockDim.x + threadIdx.x;
    if (i >= T_TOK * 2) return;
    int t = i >> 1;
    int e = d_topi[i];
    float w = d_topw[i];
    int p = atomicAdd(&d_cnt2[e], 1);
    int r = d_off[e] + p;
    d_tok[r]  = t;
    d_wrow[r] = w;
}

// ---------------- region lookup ----------------------------------------------
__device__ __forceinline__ int tile_expert(int row0) {
    if (row0 < T_TOK) return 0;
    int e = 0;
#pragma unroll
    for (int j = 0; j < NROUTED; j++)
        if (row0 >= d_off[j] && row0 < d_off[j + 1]) e = j + 1;
    return e;
}

// SMEM layout constants (floats)
#define A_STRIDE 36
#define B_STRIDE 68
#define A_STAGE  (128 * A_STRIDE)   // 4608 floats
#define B_STAGE  (32 * B_STRIDE)    // 2176 floats

// ---------------- kernel 5: fused gate+up GEMM + SiLU*u -> H -------------------
// 128x64 C-tile for BOTH wg and wu. cp.async double-buffered, TF32 mma m16n8k8.
__global__ __launch_bounds__(256, 2) void gemm1_kernel(
    const float* __restrict__ x,
    const float* __restrict__ wg,
    const float* __restrict__ wu) {
    int row0 = blockIdx.x * BM;
    if (row0 >= d_off[7]) return;
    int e = tile_expert(row0);
    const float* bg = wg + (size_t)e * D_MODEL * DFF;
    const float* bu = wu + (size_t)e * D_MODEL * DFF;
    int n0 = blockIdx.y * 64;

    extern __shared__ float smem[];
    float* sA  = smem;                       // [2][A_STAGE]
    float* sBg = sA + 2 * A_STAGE;           // [2][B_STAGE]
    float* sBu = sBg + 2 * B_STAGE;          // [2][B_STAGE]
    int*   stok = (int*)(sBu + 2 * B_STAGE); // [128]

    int tid = threadIdx.x;
    if (tid < 128) stok[tid] = d_tok[row0 + tid];
    __syncthreads();

    int warp = tid >> 5, lane = tid & 31;
    int wm = (warp >> 1) * 32, wn = (warp & 1) * 32;

    // Per-thread cp.async source precompute
    int ar[4], ac[4]; const float* asrc[4]; bool apred[4];
#pragma unroll
    for (int i = 0; i < 4; i++) {
        int f = tid + i * 256;
        ar[i] = f >> 3; ac[i] = (f & 7) << 2;
        int tok = stok[ar[i]];
        apred[i] = (tok >= 0);
        asrc[i] = x + (apred[i] ? (size_t)tok * D_MODEL + ac[i] : 0);
    }
    int br[2], bc[2];
#pragma unroll
    for (int i = 0; i < 2; i++) {
        int f = tid + i * 256;
        br[i] = f >> 4; bc[i] = (f & 15) << 2;
    }

    float accG[2][4][4], accU[2][4][4];
#pragma unroll
    for (int mi = 0; mi < 2; mi++)
#pragma unroll
        for (int ni = 0; ni < 4; ni++)
#pragma unroll
            for (int r = 0; r < 4; r++) { accG[mi][ni][r] = 0.f; accU[mi][ni][r] = 0.f; }

    // issue tile 0
    {
#pragma unroll
        for (int i = 0; i < 4; i++)
            cp16(sA + ar[i] * A_STRIDE + ac[i], asrc[i], apred[i]);
#pragma unroll
        for (int i = 0; i < 2; i++) {
            cp16(sBg + br[i] * B_STRIDE + bc[i], bg + (size_t)br[i] * DFF + n0 + bc[i], true);
            cp16(sBu + br[i] * B_STRIDE + bc[i], bu + (size_t)br[i] * DFF + n0 + bc[i], true);
        }
        cp_commit();
    }

    const int KT = D_MODEL / 32;
    for (int kt = 0; kt < KT; kt++) {
        int cur = kt & 1;
        bool has_next = (kt + 1 < KT);
        if (has_next) {
            int nk0 = (kt + 1) * 32;
            int nst = (kt + 1) & 1;
#pragma unroll
            for (int i = 0; i < 4; i++)
                cp16(sA + nst * A_STAGE + ar[i] * A_STRIDE + ac[i],
                     asrc[i] + (apred[i] ? nk0 : 0), apred[i]);
#pragma unroll
            for (int i = 0; i < 2; i++) {
                cp16(sBg + nst * B_STAGE + br[i] * B_STRIDE + bc[i],
                     bg + (size_t)(nk0 + br[i]) * DFF + n0 + bc[i], true);
                cp16(sBu + nst * B_STAGE + br[i] * B_STRIDE + bc[i],
                     bu + (size_t)(nk0 + br[i]) * DFF + n0 + bc[i], true);
            }
            cp_commit();
            cp_wait1();
        } else {
            cp_wait0();
        }
        __syncthreads();

        const float* As  = sA + cur * A_STAGE;
        const float* Bgs = sBg + cur * B_STAGE;
        const float* Bus = sBu + cur * B_STAGE;
#pragma unroll
        for (int kk = 0; kk < 32; kk += 8) {
            uint32_t a[2][4];
#pragma unroll
            for (int mi = 0; mi < 2; mi++) {
                int rb = wm + mi * 16 + (lane >> 2);
                int cb = kk + (lane & 3);
                a[mi][0] = f2tf(As[rb * A_STRIDE + cb]);
                a[mi][1] = f2tf(As[(rb + 8) * A_STRIDE + cb]);
                a[mi][2] = f2tf(As[rb * A_STRIDE + cb + 4]);
                a[mi][3] = f2tf(As[(rb + 8) * A_STRIDE + cb + 4]);
            }
#pragma unroll
            for (int ni = 0; ni < 4; ni++) {
                int nb = wn + ni * 8 + (lane >> 2);
                int kb = kk + (lane & 3);
                uint32_t bgf[2] = { f2tf(Bgs[kb * B_STRIDE + nb]), f2tf(Bgs[(kb + 4) * B_STRIDE + nb]) };
                uint32_t buf[2] = { f2tf(Bus[kb * B_STRIDE + nb]), f2tf(Bus[(kb + 4) * B_STRIDE + nb]) };
#pragma unroll
                for (int mi = 0; mi < 2; mi++) {
                    mma8(accG[mi][ni], a[mi], bgf);
                    mma8(accU[mi][ni], a[mi], buf);
                }
            }
        }
        __syncthreads();
    }
    // epilogue: H = silu(g) * u
#pragma unroll
    for (int mi = 0; mi < 2; mi++)
#pragma unroll
        for (int ni = 0; ni < 4; ni++)
#pragma unroll
            for (int rr = 0; rr < 4; rr++) {
                int rl = wm + mi * 16 + (lane >> 2) + ((rr >= 2) ? 8 : 0);
                if (stok[rl] < 0) continue;
                int col = n0 + wn + ni * 8 + 2 * (lane & 3) + (rr & 1);
                float g = accG[mi][ni][rr], u = accU[mi][ni][rr];
                float h = (g / (1.f + __expf(-g))) * u;
                d_H[(size_t)(row0 + rl) * DFF + col] = h;
            }
}

// ---------------- kernel 6: down GEMM + weighted scatter-add -------------------
__global__ __launch_bounds__(256, 2) void gemm2_kernel(
    const float* __restrict__ wd, float* __restrict__ out) {
    int row0 = blockIdx.x * BM;
    if (row0 >= d_off[7]) return;
    int e = tile_expert(row0);
    const float* bw = wd + (size_t)e * DFF * D_MODEL;
    int n0 = blockIdx.y * 64;

    extern __shared__ float smem[];
    float* sA = smem;                        // [2][A_STAGE]
    float* sB = sA + 2 * A_STAGE;            // [2][B_STAGE]
    int*   stok = (int*)(sB + 2 * B_STAGE);  // [128]
    float* swt  = (float*)(stok + 128);      // [128]

    int tid = threadIdx.x;
    if (tid < 128) { stok[tid] = d_tok[row0 + tid]; swt[tid] = d_wrow[row0 + tid]; }
    __syncthreads();

    int warp = tid >> 5, lane = tid & 31;
    int wm = (warp >> 1) * 32, wn = (warp & 1) * 32;

    int ar[4], ac[4]; bool apred[4]; const float* asrc[4];
#pragma unroll
    for (int i = 0; i < 4; i++) {
        int f = tid + i * 256;
        ar[i] = f >> 3; ac[i] = (f & 7) << 2;
        apred[i] = (stok[ar[i]] >= 0);
        asrc[i] = d_H + (size_t)(row0 + ar[i]) * DFF + ac[i];
    }
    int br[2], bc[2];
#pragma unroll
    for (int i = 0; i < 2; i++) {
        int f = tid + i * 256;
        br[i] = f >> 4; bc[i] = (f & 15) << 2;
    }

    float acc[2][4][4];
#pragma unroll
    for (int mi = 0; mi < 2; mi++)
#pragma unroll
        for (int ni = 0; ni < 4; ni++)
#pragma unroll
            for (int r = 0; r < 4; r++) acc[mi][ni][r] = 0.f;

    {
#pragma unroll
        for (int i = 0; i < 4; i++)
            cp16(sA + ar[i] * A_STRIDE + ac[i], asrc[i], apred[i]);
#pragma unroll
        for (int i = 0; i < 2; i++)
            cp16(sB + br[i] * B_STRIDE + bc[i], bw + (size_t)br[i] * D_MODEL + n0 + bc[i], true);
        cp_commit();
    }

    const int KT = DFF / 32;
    for (int kt = 0; kt < KT; kt++) {
        int cur = kt & 1;
        bool has_next = (kt + 1 < KT);
        if (has_next) {
            int nk0 = (kt + 1) * 32;
            int nst = (kt + 1) & 1;
#pragma unroll
            for (int i = 0; i < 4; i++)
                cp16(sA + nst * A_STAGE + ar[i] * A_STRIDE + ac[i],
                     asrc[i] + (apred[i] ? nk0 : 0), apred[i]);
#pragma unroll
            for (int i = 0; i < 2; i++)
                cp16(sB + nst * B_STAGE + br[i] * B_STRIDE + bc[i],
                     bw + (size_t)(nk0 + br[i]) * D_MODEL + n0 + bc[i], true);
            cp_commit();
            cp_wait1();
        } else {
            cp_wait0();
        }
        __syncthreads();

        const float* As = sA + cur * A_STAGE;
        const float* Bs = sB + cur * B_STAGE;
#pragma unroll
        for (int kk = 0; kk < 32; kk += 8) {
            uint32_t a[2][4];
#pragma unroll
            for (int mi = 0; mi < 2; mi++) {
                int rb = wm + mi * 16 + (lane >> 2);
                int cb = kk + (lane & 3);
                a[mi][0] = f2tf(As[rb * A_STRIDE + cb]);
                a[mi][1] = f2tf(As[(rb + 8) * A_STRIDE + cb]);
                a[mi][2] = f2tf(As[rb * A_STRIDE + cb + 4]);
                a[mi][3] = f2tf(As[(rb + 8) * A_STRIDE + cb + 4]);
            }
#pragma unroll
            for (int ni = 0; ni < 4; ni++) {
                int nb = wn + ni * 8 + (lane >> 2);
                int kb = kk + (lane & 3);
                uint32_t bf[2] = { f2tf(Bs[kb * B_STRIDE + nb]), f2tf(Bs[(kb + 4) * B_STRIDE + nb]) };
#pragma unroll
                for (int mi = 0; mi < 2; mi++)
                    mma8(acc[mi][ni], a[mi], bf);
            }
        }
        __syncthreads();
    }
    // epilogue: out[token] += w_row * y  (RED.ADD, after zero-init)
#pragma unroll
    for (int mi = 0; mi < 2; mi++)
#pragma unroll
        for (int ni = 0; ni < 4; ni++)
#pragma unroll
            for (int rr = 0; rr < 4; rr++) {
                int rl = wm + mi * 16 + (lane >> 2) + ((rr >= 2) ? 8 : 0);
                int tok = stok[rl];
                if (tok < 0) continue;
                int col = n0 + wn + ni * 8 + 2 * (lane & 3) + (rr & 1);
                atomicAdd(out + (size_t)tok * D_MODEL + col, swt[rl] * acc[mi][ni][rr]);
            }
}

// ---------------- launch -------------------------------------------------------
#define GEMM1_SMEM ((2 * A_STAGE + 4 * B_STAGE) * 4 + 128 * 4)
#define GEMM2_SMEM ((2 * A_STAGE + 2 * B_STAGE) * 4 + 128 * 8)

extern "C" void kernel_launch(void* const* d_in, const int* in_sizes, int n_in,
                              void* d_out, int out_size) {
    const float* x  = (const float*)d_in[0];  // hidden_states [2,2048,1024]
    const float* rw = (const float*)d_in[1];  // router_w [1024,7]
    const float* rb = (const float*)d_in[2];  // router_b [7]
    const float* wg = (const float*)d_in[3];  // [8,1024,2048]
    const float* wu = (const float*)d_in[4];  // [8,1024,2048]
    const float* wd = (const float*)d_in[5];  // [8,2048,1024]
    float* out = (float*)d_out;               // [2,2048,1024] fp32
    (void)in_sizes; (void)n_in; (void)out_size;

    static bool attr_done = false;
    if (!attr_done) {
        cudaFuncSetAttribute(gemm1_kernel, cudaFuncAttributeMaxDynamicSharedMemorySize, GEMM1_SMEM);
        cudaFuncSetAttribute(gemm2_kernel, cudaFuncAttributeMaxDynamicSharedMemorySize, GEMM2_SMEM);
        attr_done = true;
    }

    init_kernel<<<1024, 256>>>(out);
    router_kernel<<<512, 256>>>(x, rw, rb);
    offsets_kernel<<<1, 1>>>();
    fill_kernel<<<(T_TOK * 2 + 255) / 256, 256>>>();
    gemm1_kernel<<<dim3(NTILES_M, DFF / 64), 256, GEMM1_SMEM>>>(x, wg, wu);
    gemm2_kernel<<<dim3(NTILES_M, D_MODEL / 64), 256, GEMM2_SMEM>>>(wd, out);
}

// round 3
// speedup vs baseline: 1.6792x; 1.0155x over previous
#include <cuda_runtime.h>
#include <cstdint>

// Problem constants
#define T_TOK   4096
#define D_MODEL 1024
#define DFF     2048
#define NROUTED 7
#define BM      128
#define NTILES_M 104
#define R_MAX   (NTILES_M * BM)

// ---------------- scratch (static device globals; no allocations) -------------
__device__ float d_H[(size_t)R_MAX * DFF];            // hidden (tf32-rounded), ~109MB
__device__ float d_X[(size_t)T_TOK * D_MODEL];        // x tf32-rounded, 16.8MB
__device__ float d_wgT[(size_t)8 * DFF * D_MODEL];    // [E][N=DFF][K=D] tf32, 67MB
__device__ float d_wuT[(size_t)8 * DFF * D_MODEL];    // 67MB
__device__ float d_wdT[(size_t)8 * D_MODEL * DFF];    // [E][N=D][K=DFF] tf32, 67MB
__device__ int   d_tok[R_MAX];
__device__ float d_wrow[R_MAX];
__device__ int   d_off[8];
__device__ int   d_cnt[NROUTED];
__device__ int   d_cnt2[NROUTED];
__device__ int   d_topi[T_TOK * 2];
__device__ float d_topw[T_TOK * 2];

// ---------------- helpers ----------------------------------------------------
__device__ __forceinline__ uint32_t f2tf(float f) {
    uint32_t r;
    asm("cvt.rna.tf32.f32 %0, %1;" : "=r"(r) : "f"(f));
    return r;
}

__device__ __forceinline__ void mma8(float c[4], const uint32_t a[4], const uint32_t b[2]) {
    asm volatile(
        "mma.sync.aligned.m16n8k8.row.col.f32.tf32.tf32.f32 "
        "{%0,%1,%2,%3}, {%4,%5,%6,%7}, {%8,%9}, {%0,%1,%2,%3};\n"
        : "+f"(c[0]), "+f"(c[1]), "+f"(c[2]), "+f"(c[3])
        : "r"(a[0]), "r"(a[1]), "r"(a[2]), "r"(a[3]), "r"(b[0]), "r"(b[1]));
}

#define LDSM4(r0, r1, r2, r3, addr) \
    asm volatile("ldmatrix.sync.aligned.m8n8.x4.shared.b16 {%0,%1,%2,%3}, [%4];" \
                 : "=r"(r0), "=r"(r1), "=r"(r2), "=r"(r3) : "r"(addr))

__device__ __forceinline__ void cp16(float* dst, const float* src, bool pred) {
    uint32_t d = (uint32_t)__cvta_generic_to_shared(dst);
    int sz = pred ? 16 : 0;
    asm volatile("cp.async.cg.shared.global [%0], [%1], 16, %2;\n"
                 :: "r"(d), "l"(src), "r"(sz));
}
__device__ __forceinline__ void cp_commit() { asm volatile("cp.async.commit_group;\n"); }
__device__ __forceinline__ void cp_wait1()  { asm volatile("cp.async.wait_group 1;\n"); }
__device__ __forceinline__ void cp_wait0()  { asm volatile("cp.async.wait_group 0;\n"); }

// ---------------- kernel 1: init + x pre-round --------------------------------
__global__ void init_kernel(const float* __restrict__ x, float* __restrict__ out) {
    int stride = gridDim.x * blockDim.x;
    int i = blockIdx.x * blockDim.x + threadIdx.x;
    for (int j = i; j < T_TOK * D_MODEL; j += stride) {
        out[j] = 0.f;
        d_X[j] = __uint_as_float(f2tf(x[j]));
    }
    for (int j = i; j < R_MAX; j += stride) {
        if (j < T_TOK) { d_tok[j] = j;  d_wrow[j] = 1.f; }
        else           { d_tok[j] = -1; d_wrow[j] = 0.f; }
    }
    if (i < NROUTED) { d_cnt[i] = 0; d_cnt2[i] = 0; }
}

// ---------------- weight transpose + tf32 round: [E][R][C] -> [E][C][R] -------
__global__ void tr_kernel(const float* __restrict__ src, float* __restrict__ dst,
                          int R, int C) {
    __shared__ float t[32][33];
    int e = blockIdx.z;
    int c0 = blockIdx.x * 32, r0 = blockIdx.y * 32;
    const float* s = src + (size_t)e * R * C;
    float* d = dst + (size_t)e * R * C;
    int tx = threadIdx.x;
#pragma unroll
    for (int i = threadIdx.y; i < 32; i += 8)
        t[i][tx] = s[(size_t)(r0 + i) * C + c0 + tx];
    __syncthreads();
#pragma unroll
    for (int i = threadIdx.y; i < 32; i += 8)
        d[(size_t)(c0 + i) * R + r0 + tx] = __uint_as_float(f2tf(t[tx][i]));
}

// ---------------- kernel 2: router --------------------------------------------
__global__ void router_kernel(const float* __restrict__ x,
                              const float* __restrict__ rw,
                              const float* __restrict__ rb) {
    int gw = (blockIdx.x * blockDim.x + threadIdx.x) >> 5;
    int lane = threadIdx.x & 31;
    if (gw >= T_TOK) return;
    const float* xr = x + (size_t)gw * D_MODEL;
    float acc[NROUTED];
#pragma unroll
    for (int j = 0; j < NROUTED; j++) acc[j] = 0.f;
    for (int k = lane; k < D_MODEL; k += 32) {
        float xv = xr[k];
        const float* w = rw + k * NROUTED;
#pragma unroll
        for (int j = 0; j < NROUTED; j++) acc[j] += xv * w[j];
    }
#pragma unroll
    for (int j = 0; j < NROUTED; j++) {
#pragma unroll
        for (int o = 16; o > 0; o >>= 1)
            acc[j] += __shfl_xor_sync(0xffffffffu, acc[j], o);
    }
    if (lane == 0) {
        float lg[NROUTED];
#pragma unroll
        for (int j = 0; j < NROUTED; j++) lg[j] = acc[j] + rb[j];
        int i1 = 0;
#pragma unroll
        for (int j = 1; j < NROUTED; j++) if (lg[j] > lg[i1]) i1 = j;
        int i2 = (i1 == 0) ? 1 : 0;
#pragma unroll
        for (int j = 0; j < NROUTED; j++)
            if (j != i1 && lg[j] > lg[i2]) i2 = j;
        float m  = fmaxf(lg[i1], lg[i2]);
        float e1 = expf(lg[i1] - m), e2 = expf(lg[i2] - m);
        float s  = e1 + e2;
        d_topi[gw * 2] = i1;  d_topi[gw * 2 + 1] = i2;
        d_topw[gw * 2] = e1 / s;  d_topw[gw * 2 + 1] = e2 / s;
        atomicAdd(&d_cnt[i1], 1);
        atomicAdd(&d_cnt[i2], 1);
    }
}

// ---------------- kernel 3 + 4 -------------------------------------------------
__global__ void offsets_kernel() {
    if (threadIdx.x == 0 && blockIdx.x == 0) {
        int base = T_TOK;
        for (int j = 0; j < NROUTED; j++) {
            d_off[j] = base;
            base += ((d_cnt[j] + BM - 1) / BM) * BM;
        }
        d_off[7] = base;
    }
}

__global__ void fill_kernel() {
    int i = blockIdx.x * blockDim.x + threadIdx.x;
    if (i >= T_TOK * 2) return;
    int t = i >> 1;
    int e = d_topi[i];
    float w = d_topw[i];
    int p = atomicAdd(&d_cnt2[e], 1);
    int r = d_off[e] + p;
    d_tok[r]  = t;
    d_wrow[r] = w;
}

__device__ __forceinline__ int tile_expert(int row0) {
    if (row0 < T_TOK) return 0;
    int e = 0;
#pragma unroll
    for (int j = 0; j < NROUTED; j++)
        if (row0 >= d_off[j] && row0 < d_off[j + 1]) e = j + 1;
    return e;
}

// ---------------- GEMM tiles: BM=128, BN=128, BK=32, 512 thr (4x4 warps) ------
#define STRIDE 36
#define ASTG   (128 * STRIDE)        // floats per stage (A or one B operand)

// ---------------- kernel 5: fused gate+up GEMM + SiLU*u -> H -------------------
__global__ __launch_bounds__(512, 1) void gemm1_kernel() {
    int row0 = blockIdx.x * BM;
    if (row0 >= d_off[7]) return;
    int e = tile_expert(row0);
    const float* bg = d_wgT + (size_t)e * DFF * D_MODEL;   // [N=DFF][K=D]
    const float* bu = d_wuT + (size_t)e * DFF * D_MODEL;
    int n0 = blockIdx.y * 128;

    extern __shared__ float smem[];
    float* sA  = smem;                 // [2][ASTG]
    float* sBg = sA + 2 * ASTG;        // [2][ASTG]
    float* sBu = sBg + 2 * ASTG;       // [2][ASTG]
    int*   stok = (int*)(sBu + 2 * ASTG);

    int tid = threadIdx.x;
    if (tid < 128) stok[tid] = d_tok[row0 + tid];
    __syncthreads();

    int warp = tid >> 5, lane = tid & 31;
    int wm = (warp >> 2) * 32, wn = (warp & 3) * 32;

    // cp.async chunk mapping: 1024 chunks per tile, 2 per thread
    int ar[2], ac[2]; const float* asrcA[2]; bool apred[2];
    const float* srcG[2]; const float* srcU[2];
#pragma unroll
    for (int i = 0; i < 2; i++) {
        int f = tid + i * 512;
        ar[i] = f >> 3; ac[i] = (f & 7) << 2;
        int tok = stok[ar[i]];
        apred[i] = (tok >= 0);
        asrcA[i] = d_X + (apred[i] ? (size_t)tok * D_MODEL + ac[i] : 0);
        srcG[i] = bg + (size_t)(n0 + ar[i]) * D_MODEL + ac[i];
        srcU[i] = bu + (size_t)(n0 + ar[i]) * D_MODEL + ac[i];
    }

    // ldmatrix address precompute (byte addresses in shared space)
    uint32_t sbase = (uint32_t)__cvta_generic_to_shared(smem);
    int arow = 8 * ((lane >> 3) & 1) + (lane & 7);
    int acol = 4 * (lane >> 4);
    uint32_t aaddr[2];
#pragma unroll
    for (int mi = 0; mi < 2; mi++)
        aaddr[mi] = sbase + ((wm + mi * 16 + arow) * STRIDE + acol) * 4;
    int brow = 8 * (lane >> 4) + (lane & 7);
    int bcol = 4 * ((lane >> 3) & 1);
    uint32_t gaddr[2], uaddr[2];
#pragma unroll
    for (int p = 0; p < 2; p++) {
        uint32_t off = ((wn + p * 16 + brow) * STRIDE + bcol) * 4;
        gaddr[p] = sbase + 2 * ASTG * 4 + off;
        uaddr[p] = sbase + 4 * ASTG * 4 + off;
    }

    float accG[2][4][4], accU[2][4][4];
#pragma unroll
    for (int mi = 0; mi < 2; mi++)
#pragma unroll
        for (int ni = 0; ni < 4; ni++)
#pragma unroll
            for (int r = 0; r < 4; r++) { accG[mi][ni][r] = 0.f; accU[mi][ni][r] = 0.f; }

    // stage 0 prefetch
#pragma unroll
    for (int i = 0; i < 2; i++) {
        cp16(sA + ar[i] * STRIDE + ac[i], asrcA[i], apred[i]);
        cp16(sBg + ar[i] * STRIDE + ac[i], srcG[i], true);
        cp16(sBu + ar[i] * STRIDE + ac[i], srcU[i], true);
    }
    cp_commit();

    const int KT = D_MODEL / 32;
    for (int kt = 0; kt < KT; kt++) {
        int cur = kt & 1;
        if (kt + 1 < KT) {
            int nk0 = (kt + 1) * 32;
            int nst = (kt + 1) & 1;
#pragma unroll
            for (int i = 0; i < 2; i++) {
                cp16(sA + nst * ASTG + ar[i] * STRIDE + ac[i],
                     asrcA[i] + (apred[i] ? nk0 : 0), apred[i]);
                cp16(sBg + nst * ASTG + ar[i] * STRIDE + ac[i], srcG[i] + nk0, true);
                cp16(sBu + nst * ASTG + ar[i] * STRIDE + ac[i], srcU[i] + nk0, true);
            }
            cp_commit();
            cp_wait1();
        } else {
            cp_wait0();
        }
        __syncthreads();

        uint32_t sb = cur * ASTG * 4;
#pragma unroll
        for (int kk = 0; kk < 32; kk += 8) {
            uint32_t a[2][4];
            LDSM4(a[0][0], a[0][1], a[0][2], a[0][3], aaddr[0] + sb + kk * 4);
            LDSM4(a[1][0], a[1][1], a[1][2], a[1][3], aaddr[1] + sb + kk * 4);
#pragma unroll
            for (int p = 0; p < 2; p++) {
                uint32_t g4[4], u4[4];
                LDSM4(g4[0], g4[1], g4[2], g4[3], gaddr[p] + sb + kk * 4);
                LDSM4(u4[0], u4[1], u4[2], u4[3], uaddr[p] + sb + kk * 4);
                mma8(accG[0][2 * p],     a[0], g4 + 0);
                mma8(accG[1][2 * p],     a[1], g4 + 0);
                mma8(accG[0][2 * p + 1], a[0], g4 + 2);
                mma8(accG[1][2 * p + 1], a[1], g4 + 2);
                mma8(accU[0][2 * p],     a[0], u4 + 0);
                mma8(accU[1][2 * p],     a[1], u4 + 0);
                mma8(accU[0][2 * p + 1], a[0], u4 + 2);
                mma8(accU[1][2 * p + 1], a[1], u4 + 2);
            }
        }
        __syncthreads();
    }
    // epilogue: H = tf32_round(silu(g) * u)
#pragma unroll
    for (int mi = 0; mi < 2; mi++)
#pragma unroll
        for (int ni = 0; ni < 4; ni++)
#pragma unroll
            for (int rr = 0; rr < 4; rr++) {
                int rl = wm + mi * 16 + (lane >> 2) + ((rr >= 2) ? 8 : 0);
                if (stok[rl] < 0) continue;
                int col = n0 + wn + ni * 8 + 2 * (lane & 3) + (rr & 1);
                float g = accG[mi][ni][rr], u = accU[mi][ni][rr];
                float h = (g / (1.f + __expf(-g))) * u;
                d_H[(size_t)(row0 + rl) * DFF + col] = __uint_as_float(f2tf(h));
            }
}

// ---------------- kernel 6: down GEMM + weighted scatter-add -------------------
__global__ __launch_bounds__(512, 1) void gemm2_kernel(float* __restrict__ out) {
    int row0 = blockIdx.x * BM;
    if (row0 >= d_off[7]) return;
    int e = tile_expert(row0);
    const float* bw = d_wdT + (size_t)e * DFF * D_MODEL;   // [N=D][K=DFF]
    int n0 = blockIdx.y * 128;

    extern __shared__ float smem[];
    float* sA = smem;                 // [2][ASTG]
    float* sB = sA + 2 * ASTG;        // [2][ASTG]
    int*   stok = (int*)(sB + 2 * ASTG);
    float* swt  = (float*)(stok + 128);

    int tid = threadIdx.x;
    if (tid < 128) { stok[tid] = d_tok[row0 + tid]; swt[tid] = d_wrow[row0 + tid]; }
    __syncthreads();

    int warp = tid >> 5, lane = tid & 31;
    int wm = (warp >> 2) * 32, wn = (warp & 3) * 32;

    int ar[2], ac[2]; bool apred[2]; const float* asrcA[2]; const float* srcB[2];
#pragma unroll
    for (int i = 0; i < 2; i++) {
        int f = tid + i * 512;
        ar[i] = f >> 3; ac[i] = (f & 7) << 2;
        apred[i] = (stok[ar[i]] >= 0);
        asrcA[i] = d_H + (size_t)(row0 + ar[i]) * DFF + ac[i];
        srcB[i] = bw + (size_t)(n0 + ar[i]) * DFF + ac[i];
    }

    uint32_t sbase = (uint32_t)__cvta_generic_to_shared(smem);
    int arow = 8 * ((lane >> 3) & 1) + (lane & 7);
    int acol = 4 * (lane >> 4);
    uint32_t aaddr[2];
#pragma unroll
    for (int mi = 0; mi < 2; mi++)
        aaddr[mi] = sbase + ((wm + mi * 16 + arow) * STRIDE + acol) * 4;
    int brow = 8 * (lane >> 4) + (lane & 7);
    int bcol = 4 * ((lane >> 3) & 1);
    uint32_t baddr[2];
#pragma unroll
    for (int p = 0; p < 2; p++)
        baddr[p] = sbase + 2 * ASTG * 4 + ((wn + p * 16 + brow) * STRIDE + bcol) * 4;

    float acc[2][4][4];
#pragma unroll
    for (int mi = 0; mi < 2; mi++)
#pragma unroll
        for (int ni = 0; ni < 4; ni++)
#pragma unroll
            for (int r = 0; r < 4; r++) acc[mi][ni][r] = 0.f;

#pragma unroll
    for (int i = 0; i < 2; i++) {
        cp16(sA + ar[i] * STRIDE + ac[i], asrcA[i], apred[i]);
        cp16(sB + ar[i] * STRIDE + ac[i], srcB[i], true);
    }
    cp_commit();

    const int KT = DFF / 32;
    for (int kt = 0; kt < KT; kt++) {
        int cur = kt & 1;
        if (kt + 1 < KT) {
            int nk0 = (kt + 1) * 32;
            int nst = (kt + 1) & 1;
#pragma unroll
            for (int i = 0; i < 2; i++) {
                cp16(sA + nst * ASTG + ar[i] * STRIDE + ac[i],
                     asrcA[i] + (apred[i] ? nk0 : 0), apred[i]);
                cp16(sB + nst * ASTG + ar[i] * STRIDE + ac[i], srcB[i] + nk0, true);
            }
            cp_commit();
            cp_wait1();
        } else {
            cp_wait0();
        }
        __syncthreads();

        uint32_t sb = cur * ASTG * 4;
#pragma unroll
        for (int kk = 0; kk < 32; kk += 8) {
            uint32_t a[2][4];
            LDSM4(a[0][0], a[0][1], a[0][2], a[0][3], aaddr[0] + sb + kk * 4);
            LDSM4(a[1][0], a[1][1], a[1][2], a[1][3], aaddr[1] + sb + kk * 4);
#pragma unroll
            for (int p = 0; p < 2; p++) {
                uint32_t b4[4];
                LDSM4(b4[0], b4[1], b4[2], b4[3], baddr[p] + sb + kk * 4);
                mma8(acc[0][2 * p],     a[0], b4 + 0);
                mma8(acc[1][2 * p],     a[1], b4 + 0);
                mma8(acc[0][2 * p + 1], a[0], b4 + 2);
                mma8(acc[1][2 * p + 1], a[1], b4 + 2);
            }
        }
        __syncthreads();
    }
#pragma unroll
    for (int mi = 0; mi < 2; mi++)
#pragma unroll
        for (int ni = 0; ni < 4; ni++)
#pragma unroll
            for (int rr = 0; rr < 4; rr++) {
                int rl = wm + mi * 16 + (lane >> 2) + ((rr >= 2) ? 8 : 0);
                int tok = stok[rl];
                if (tok < 0) continue;
                int col = n0 + wn + ni * 8 + 2 * (lane & 3) + (rr & 1);
                atomicAdd(out + (size_t)tok * D_MODEL + col, swt[rl] * acc[mi][ni][rr]);
            }
}

// ---------------- launch -------------------------------------------------------
#define GEMM1_SMEM (6 * ASTG * 4 + 128 * 4)
#define GEMM2_SMEM (4 * ASTG * 4 + 128 * 8)

extern "C" void kernel_launch(void* const* d_in, const int* in_sizes, int n_in,
                              void* d_out, int out_size) {
    const float* x  = (const float*)d_in[0];
    const float* rw = (const float*)d_in[1];
    const float* rb = (const float*)d_in[2];
    const float* wg = (const float*)d_in[3];
    const float* wu = (const float*)d_in[4];
    const float* wd = (const float*)d_in[5];
    float* out = (float*)d_out;
    (void)in_sizes; (void)n_in; (void)out_size;

    static bool attr_done = false;
    if (!attr_done) {
        cudaFuncSetAttribute(gemm1_kernel, cudaFuncAttributeMaxDynamicSharedMemorySize, GEMM1_SMEM);
        cudaFuncSetAttribute(gemm2_kernel, cudaFuncAttributeMaxDynamicSharedMemorySize, GEMM2_SMEM);
        attr_done = true;
    }

    // pointers to device globals for prep kernels
    float *pwgT, *pwuT, *pwdT;
    cudaGetSymbolAddress((void**)&pwgT, d_wgT);
    cudaGetSymbolAddress((void**)&pwuT, d_wuT);
    cudaGetSymbolAddress((void**)&pwdT, d_wdT);

    init_kernel<<<1024, 256>>>(x, out);
    router_kernel<<<512, 256>>>(x, rw, rb);
    offsets_kernel<<<1, 1>>>();
    fill_kernel<<<(T_TOK * 2 + 255) / 256, 256>>>();
    // weight transpose + tf32 round: [E][K][N] -> [E][N][K]
    tr_kernel<<<dim3(DFF / 32, D_MODEL / 32, 8), dim3(32, 8)>>>(wg, pwgT, D_MODEL, DFF);
    tr_kernel<<<dim3(DFF / 32, D_MODEL / 32, 8), dim3(32, 8)>>>(wu, pwuT, D_MODEL, DFF);
    tr_kernel<<<dim3(D_MODEL / 32, DFF / 32, 8), dim3(32, 8)>>>(wd, pwdT, DFF, D_MODEL);
    gemm1_kernel<<<dim3(NTILES_M, DFF / 128), 512, GEMM1_SMEM>>>();
    gemm2_kernel<<<dim3(NTILES_M, D_MODEL / 128), 512, GEMM2_SMEM>>>(out);
}